// round 9
// baseline (speedup 1.0000x reference)
#include <cuda_runtime.h>
#include <cstdint>

#define Bn 32
#define Ln 4096
#define Fn 128
#define NLEV 12
#define NSPLIT 16
#define TILE_L 64
#define TILES_PER_CTA 4
#define GRIDX 16                         // 16 * 4 * 64 = 4096 rows
#define TOT (Bn * Ln * Fn)

// GEMM smem: A double buffer 2 x 64x132 floats, red 512 floats
#define FO_A1 8448
#define FO_RED 16896
#define GEMM_SMEM ((16896 + 512) * 4)    // 69632 bytes

#define ATT_SMEM (128 * 132 * 4 + 1024)

// ---------------- scratch ----------------
__device__ float g_coef[2][Ln];
__device__ float g_bias[2];
__device__ float g_part[Bn][NSPLIT][2][Fn];
__device__ float g_x2[TOT];
__device__ float g_y3[TOT];
__device__ float g_stat[Bn][GRIDX][2][Fn];
__device__ float g_sc[Bn][Fn];
__device__ float g_sh[Bn][Fn];
__device__ float g_rsh[Bn][Fn];              // sh + ffb + sh@W^T
__device__ float2 g_Bp0[Bn][8192];           // packed tf32 B frags (GEMM0: att^T)
__device__ float2 g_Bp1[Bn][8192];           // packed tf32 B frags (GEMM1: sc*W)

__device__ __forceinline__ uint32_t smem_u32(const void* p) {
    uint32_t a;
    asm("{ .reg .u64 t; cvta.to.shared.u64 t, %1; cvt.u32.u64 %0, t; }" : "=r"(a) : "l"(p));
    return a;
}
__device__ __forceinline__ uint32_t f2tf32(float x) {
    uint32_t r;
    asm("cvt.rna.tf32.f32 %0, %1;" : "=r"(r) : "f"(x));
    return r;
}
__device__ __forceinline__ void cp16(uint32_t dst, const void* src) {
    asm volatile("cp.async.cg.shared.global [%0], [%1], 16;" :: "r"(dst), "l"(src));
}
#define CP_COMMIT() asm volatile("cp.async.commit_group;" ::: "memory")
#define CP_WAIT1()  asm volatile("cp.async.wait_group 1;" ::: "memory")

#define LDSM4(r0, r1, r2, r3, addr) \
    asm volatile("ldmatrix.sync.aligned.m8n8.x4.shared.b16 {%0,%1,%2,%3}, [%4];" \
                 : "=r"(r0), "=r"(r1), "=r"(r2), "=r"(r3) : "r"(addr))

#define MMA_TF32(C, A, b0, b1) \
    asm volatile("mma.sync.aligned.m16n8k8.row.col.f32.tf32.tf32.f32 " \
                 "{%0,%1,%2,%3}, {%4,%5,%6,%7}, {%8,%9}, {%0,%1,%2,%3};" \
                 : "+f"(C[0]), "+f"(C[1]), "+f"(C[2]), "+f"(C[3]) \
                 : "r"(A[0]), "r"(A[1]), "r"(A[2]), "r"(A[3]), "r"(b0), "r"(b1))

// ---------------- 1) wavelet coefficients + biases ----------------
__global__ void coef_kernel(const float* __restrict__ qw, const float* __restrict__ qb,
                            const float* __restrict__ kw, const float* __restrict__ kb) {
    int l = blockIdx.x * blockDim.x + threadIdx.x;
    if (l < Ln) {
        float cq = 1.f, ck = 1.f;
        #pragma unroll
        for (int i = 0; i < NLEV; i++) {
            int bit = (l >> i) & 1;
            cq *= qw[2 * i + bit];
            ck *= kw[2 * i + bit];
        }
        g_coef[0][l] = cq;
        g_coef[1][l] = ck;
    }
    if (blockIdx.x == 0 && threadIdx.x == 0) {
        float bq = qb[NLEV - 1], bk = kb[NLEV - 1], pq = 1.f, pk = 1.f;
        for (int i = NLEV - 2; i >= 0; i--) {
            pq *= (qw[2 * (i + 1)] + qw[2 * (i + 1) + 1]);
            pk *= (kw[2 * (i + 1)] + kw[2 * (i + 1) + 1]);
            bq += qb[i] * pq;
            bk += kb[i] * pk;
        }
        g_bias[0] = bq;
        g_bias[1] = bk;
    }
}

// ---------------- 2) q/k partial reductions over L ----------------
__global__ void qk_partial(const float* __restrict__ x) {
    const int b = blockIdx.y, ls = blockIdx.x;
    const int tid = threadIdx.x;
    const int f = tid & 127, sub = tid >> 7;
    const int lbase = ls * 256 + sub * 128;
    const float* xp = x + ((size_t)b * Ln + lbase) * Fn + f;
    float aq = 0.f, ak = 0.f;
    #pragma unroll 8
    for (int j = 0; j < 128; j++) {
        float xv = xp[(size_t)j * Fn];
        int l = lbase + j;
        aq = fmaf(g_coef[0][l], xv, aq);
        ak = fmaf(g_coef[1][l], xv, ak);
    }
    __shared__ float sq[256], sk[256];
    sq[tid] = aq; sk[tid] = ak;
    __syncthreads();
    if (tid < 128) {
        g_part[b][ls][0][tid] = sq[tid] + sq[tid + 128];
        g_part[b][ls][1][tid] = sk[tid] + sk[tid + 128];
    }
}

// ---------------- 3) fused: q/k finalize + softmax + packed B0 ----------------
__global__ void att_prep() {
    extern __shared__ float sm[];
    float* at   = sm;                 // 128 x 132 exp values
    float* kk   = sm + 128 * 132;
    float* rinv = kk + 128;
    const int b = blockIdx.x, f = threadIdx.x;

    float q = g_bias[0], k = g_bias[1];
    #pragma unroll
    for (int s = 0; s < NSPLIT; s++) {
        q += g_part[b][s][0][f];
        k += g_part[b][s][1][f];
    }
    kk[f] = k;
    __syncthreads();

    const float t = q * 0.08838834764831845f;
    float m = -1e30f;
    #pragma unroll 4
    for (int g = 0; g < 128; g++) m = fmaxf(m, t * kk[g]);
    float sum = 0.f;
    #pragma unroll 4
    for (int g = 0; g < 128; g++) {
        float e = expf(t * kk[g] - m);
        at[f * 132 + g] = e;
        sum += e;
    }
    rinv[f] = 1.f / sum;
    __syncthreads();

    // packed fragment table: B0[n][k] = att[k][n]*rinv[k]
    for (int idx = f; idx < 8192; idx += 128) {
        int blk = idx >> 5, li = idx & 31;
        int wn = blk >> 6, ni = (blk >> 4) & 3, ks = blk & 15;
        int gd = li >> 2, tg = li & 3;
        int n = wn * 32 + ni * 8 + gd;
        int k0 = ks * 8 + tg;
        float v0 = at[k0 * 132 + n] * rinv[k0];
        float v1 = at[(k0 + 4) * 132 + n] * rinv[k0 + 4];
        g_Bp0[b][idx] = make_float2(__uint_as_float(f2tf32(v0)), __uint_as_float(f2tf32(v1)));
    }
}

// ---------------- 4) fused: stat finalize + GEMM1 operand prep ----------------
__global__ void prep2(const float* __restrict__ ffw, const float* __restrict__ ffb,
                      const float* __restrict__ gamma, const float* __restrict__ beta) {
    __shared__ float ssh[Fn], ssc[Fn];
    const int b = blockIdx.x, g = threadIdx.x;
    float s = 0.f, q = 0.f;
    #pragma unroll
    for (int t = 0; t < GRIDX; t++) {
        s += g_stat[b][t][0][g];
        q += g_stat[b][t][1][g];
    }
    const float inv = 1.f / (float)Ln;
    float m = s * inv;
    float v = q * inv - m * m;
    float rs = rsqrtf(v + 1e-5f);
    float sc = rs * gamma[g];
    float sh = fmaf(-m, sc, beta[g]);
    g_sc[b][g] = sc;
    ssc[g] = sc; ssh[g] = sh;
    __syncthreads();
    float bias2 = ffb[g];
    #pragma unroll 4
    for (int k = 0; k < Fn; k++) bias2 = fmaf(ssh[k], ffw[g * Fn + k], bias2);
    g_rsh[b][g] = ssh[g] + bias2;
    // packed fragment table: B1[n][k] = ffw[n][k]*sc[k]
    for (int idx = g; idx < 8192; idx += 128) {
        int blk = idx >> 5, li = idx & 31;
        int wn = blk >> 6, ni = (blk >> 4) & 3, ks = blk & 15;
        int gd = li >> 2, tg = li & 3;
        int n = wn * 32 + ni * 8 + gd;
        int k0 = ks * 8 + tg;
        float v0 = ffw[n * Fn + k0] * ssc[k0];
        float v1 = ffw[n * Fn + k0 + 4] * ssc[k0 + 4];
        g_Bp1[b][idx] = make_float2(__uint_as_float(f2tf32(v0)), __uint_as_float(f2tf32(v1)));
    }
}

// ---------------- 5) tf32 GEMM: 64x128 tiles, ldmatrix A, LDG B, 3 CTA/SM ----------------
// out = (A @ B^T) + A*rsc + rsh ; MODE0: rsc=1, rsh=0
template <int MODE>
__global__ __launch_bounds__(256, 3)
void mma_gemm(const float* __restrict__ xin) {
    extern __shared__ float sm[];
    float* const Abuf[2] = { sm, sm + FO_A1 };
    float4* const red = (float4*)(sm + FO_RED);

    const int tid = threadIdx.x, lane = tid & 31, w = tid >> 5;
    const int gid = lane >> 2, tig = lane & 3;
    const int wn = w & 3, wm = w >> 2;           // 2 wm x 4 wn, warp tile 32x32
    const int b = blockIdx.y;

    const size_t base = ((size_t)b * Ln + (size_t)blockIdx.x * TILES_PER_CTA * TILE_L) * Fn;
    const float* Xin = (MODE == 0 ? xin : g_x2) + base;
    float* Xout = (MODE == 0 ? g_x2 : g_y3) + base;

    const uint32_t ab32[2] = { smem_u32(Abuf[0]), smem_u32(Abuf[1]) };

    // ldmatrix per-thread source offset within A buffer (bytes)
    const uint32_t lrow = lane & 15;             // matrices 0/1 -> rows 0-15
    const uint32_t lcol = (lane >> 4) * 4;       // matrices 2/3 -> +4 words
    const uint32_t aoff = ((wm * 32 + lrow) * 132 + lcol) * 4;

    // packed B fragment pointer: this thread's lane slot for (wn, ni=0, ks=0)
    const float2* Bp = (MODE == 0 ? &g_Bp0[b][0] : &g_Bp1[b][0]) + (wn * 4 * 16) * 32 + lane;

    // prologue: cp.async tile 0 (64x128 floats)
    #pragma unroll
    for (int i = tid; i < 2048; i += 256)
        cp16(ab32[0] + ((i >> 5) * 132 + (i & 31) * 4) * 4, Xin + (size_t)i * 4);
    CP_COMMIT();

    // epilogue affine params
    float2 rsc2[4], rsh2[4];
    #pragma unroll
    for (int ni = 0; ni < 4; ni++) {
        if (MODE == 1) {
            int col = wn * 32 + ni * 8 + tig * 2;
            rsc2[ni] = *(const float2*)&g_sc[b][col];
            rsh2[ni] = *(const float2*)&g_rsh[b][col];
        } else {
            rsc2[ni] = make_float2(1.f, 1.f);
            rsh2[ni] = make_float2(0.f, 0.f);
        }
    }

    float2 st_s[4], st_q[4];
    #pragma unroll
    for (int ni = 0; ni < 4; ni++) {
        st_s[ni] = make_float2(0.f, 0.f);
        st_q[ni] = make_float2(0.f, 0.f);
    }

    for (int t = 0; t < TILES_PER_CTA; t++) {
        if (t + 1 < TILES_PER_CTA) {
            const float* src = Xin + (size_t)(t + 1) * TILE_L * Fn;
            #pragma unroll
            for (int i = tid; i < 2048; i += 256)
                cp16(ab32[(t + 1) & 1] + ((i >> 5) * 132 + (i & 31) * 4) * 4, src + (size_t)i * 4);
        }
        CP_COMMIT();
        CP_WAIT1();
        __syncthreads();

        const uint32_t abase = ab32[t & 1] + aoff;
        float* const buf = Abuf[t & 1];

        float c[2][4][4];
        #pragma unroll
        for (int mi = 0; mi < 2; mi++)
            #pragma unroll
            for (int ni = 0; ni < 4; ni++)
                #pragma unroll
                for (int j = 0; j < 4; j++) c[mi][ni][j] = 0.f;

        #pragma unroll
        for (int ks = 0; ks < 16; ks++) {
            uint32_t a[2][4];
            LDSM4(a[0][0], a[0][1], a[0][2], a[0][3], abase + ks * 32);
            LDSM4(a[1][0], a[1][1], a[1][2], a[1][3], abase + 16 * 132 * 4 + ks * 32);
            #pragma unroll
            for (int mi = 0; mi < 2; mi++)
                #pragma unroll
                for (int j = 0; j < 4; j++)
                    a[mi][j] = f2tf32(__uint_as_float(a[mi][j]));
            #pragma unroll
            for (int ni = 0; ni < 4; ni++) {
                float2 bv = __ldg(Bp + (ni * 16 + ks) * 32);
                uint32_t b0 = __float_as_uint(bv.x), b1 = __float_as_uint(bv.y);
                MMA_TF32(c[0][ni], a[0], b0, b1);
                MMA_TF32(c[1][ni], a[1], b0, b1);
            }
        }

        // direct epilogue: residual from A smem, STG to gmem, stats in regs
        float* Yt = Xout + (size_t)t * TILE_L * Fn;
        #pragma unroll
        for (int mi = 0; mi < 2; mi++)
            #pragma unroll
            for (int ni = 0; ni < 4; ni++) {
                const int r0 = wm * 32 + mi * 16 + gid;
                const int col = wn * 32 + ni * 8 + tig * 2;
                float2 x0 = *(float2*)&buf[r0 * 132 + col];
                float2 x1 = *(float2*)&buf[(r0 + 8) * 132 + col];
                float2 o0, o1;
                o0.x = c[mi][ni][0] + fmaf(x0.x, rsc2[ni].x, rsh2[ni].x);
                o0.y = c[mi][ni][1] + fmaf(x0.y, rsc2[ni].y, rsh2[ni].y);
                o1.x = c[mi][ni][2] + fmaf(x1.x, rsc2[ni].x, rsh2[ni].x);
                o1.y = c[mi][ni][3] + fmaf(x1.y, rsc2[ni].y, rsh2[ni].y);
                *(float2*)&Yt[(size_t)r0 * Fn + col] = o0;
                *(float2*)&Yt[(size_t)(r0 + 8) * Fn + col] = o1;
                st_s[ni].x += o0.x + o1.x;
                st_s[ni].y += o0.y + o1.y;
                st_q[ni].x += fmaf(o0.x, o0.x, o1.x * o1.x);
                st_q[ni].y += fmaf(o0.y, o0.y, o1.y * o1.y);
            }
        __syncthreads();   // buf reads done before prefetch of t+2 overwrites
    }

    // stats: shfl over gid, then cross-wm via smem
    #pragma unroll
    for (int ni = 0; ni < 4; ni++) {
        #pragma unroll
        for (int off = 4; off < 32; off <<= 1) {
            st_s[ni].x += __shfl_xor_sync(0xFFFFFFFFu, st_s[ni].x, off);
            st_s[ni].y += __shfl_xor_sync(0xFFFFFFFFu, st_s[ni].y, off);
            st_q[ni].x += __shfl_xor_sync(0xFFFFFFFFu, st_q[ni].x, off);
            st_q[ni].y += __shfl_xor_sync(0xFFFFFFFFu, st_q[ni].y, off);
        }
        if (gid == 0)
            red[w * 16 + ni * 4 + tig] = make_float4(st_s[ni].x, st_s[ni].y, st_q[ni].x, st_q[ni].y);
    }
    __syncthreads();
    if (tid < 128) {
        const int f = tid;
        const int fwn = f >> 5, fni = (f >> 3) & 3, ftg = (f >> 1) & 3, xy = f & 1;
        float s = 0.f, q = 0.f;
        #pragma unroll
        for (int m = 0; m < 2; m++) {   // over wm
            float4 v = red[(m * 4 + fwn) * 16 + fni * 4 + ftg];
            s += xy ? v.y : v.x;
            q += xy ? v.w : v.z;
        }
        g_stat[b][blockIdx.x][0][f] = s;
        g_stat[b][blockIdx.x][1][f] = q;
    }
}

// ---------------- 6) stats -> scale/shift (for final norm) ----------------
__global__ void stat_reduce(const float* __restrict__ gamma, const float* __restrict__ beta) {
    const int b = blockIdx.x, g = threadIdx.x;
    float s = 0.f, q = 0.f;
    #pragma unroll
    for (int t = 0; t < GRIDX; t++) {
        s += g_stat[b][t][0][g];
        q += g_stat[b][t][1][g];
    }
    const float inv = 1.f / (float)Ln;
    float m = s * inv;
    float v = q * inv - m * m;
    float rs = rsqrtf(v + 1e-5f);
    float sc = rs * gamma[g];
    g_sc[b][g] = sc;
    g_sh[b][g] = fmaf(-m, sc, beta[g]);
}

// ---------------- 7) final normalize ----------------
__global__ void final_kernel(float* __restrict__ out) {
    int i = blockIdx.x * blockDim.x + threadIdx.x;
    int b = i >> 17;
    int fq = i & 31;
    float4 v = ((const float4*)g_y3)[i];
    float4 s = ((const float4*)&g_sc[b][0])[fq];
    float4 h = ((const float4*)&g_sh[b][0])[fq];
    v.x = fmaf(v.x, s.x, h.x); v.y = fmaf(v.y, s.y, h.y);
    v.z = fmaf(v.z, s.z, h.z); v.w = fmaf(v.w, s.w, h.w);
    ((float4*)out)[i] = v;
}

// ---------------- launch ----------------
extern "C" void kernel_launch(void* const* d_in, const int* in_sizes, int n_in,
                              void* d_out, int out_size) {
    const float* x     = (const float*)d_in[0];
    const float* qw    = (const float*)d_in[1];
    const float* qb    = (const float*)d_in[2];
    const float* kw    = (const float*)d_in[3];
    const float* kb    = (const float*)d_in[4];
    const float* ffw   = (const float*)d_in[5];
    const float* ffb   = (const float*)d_in[6];
    const float* gamma = (const float*)d_in[7];
    const float* beta  = (const float*)d_in[8];
    float* out = (float*)d_out;

    cudaFuncSetAttribute((const void*)mma_gemm<0>,
                         cudaFuncAttributeMaxDynamicSharedMemorySize, GEMM_SMEM);
    cudaFuncSetAttribute((const void*)mma_gemm<1>,
                         cudaFuncAttributeMaxDynamicSharedMemorySize, GEMM_SMEM);
    cudaFuncSetAttribute((const void*)att_prep,
                         cudaFuncAttributeMaxDynamicSharedMemorySize, ATT_SMEM);

    coef_kernel<<<(Ln + 255) / 256, 256>>>(qw, qb, kw, kb);
    qk_partial<<<dim3(NSPLIT, Bn), 256>>>(x);
    att_prep<<<Bn, 128, ATT_SMEM>>>();
    mma_gemm<0><<<dim3(GRIDX, Bn), 256, GEMM_SMEM>>>(x);
    prep2<<<Bn, Fn>>>(ffw, ffb, gamma, beta);
    mma_gemm<1><<<dim3(GRIDX, Bn), 256, GEMM_SMEM>>>(x);
    stat_reduce<<<Bn, Fn>>>(gamma, beta);
    final_kernel<<<TOT / 4 / 256, 256>>>(out);
}

// round 10
// speedup vs baseline: 1.1854x; 1.1854x over previous
#include <cuda_runtime.h>
#include <cstdint>

#define Bn 32
#define Ln 4096
#define Fn 128
#define NLEV 12
#define NSPLIT 16
#define TILE_L 128
#define TILES_PER_CTA 8
#define GRIDX 4                          // 4 * 8 * 128 = 4096 rows
#define TOT (Bn * Ln * Fn)

// GEMM smem: A double buffer 2 x 128x132 floats, red 1024 floats
#define FO_A1 16896
#define FO_RED 33792
#define GEMM_SMEM ((33792 + 1024) * 4)   // 139264 bytes

// ---------------- scratch ----------------
__device__ float g_coef[2][Ln];
__device__ float g_bias[2];
__device__ float g_part[Bn][NSPLIT][2][Fn];
__device__ float g_qs[Bn][Fn];               // q * 1/sqrt(F)
__device__ float g_kv[Bn][Fn];
__device__ float g_x2[TOT];
__device__ float g_y3[TOT];
__device__ float g_stat[Bn][GRIDX][2][Fn];
__device__ float g_sc[Bn][Fn];
__device__ float g_sh[Bn][Fn];
__device__ float g_rsh[Bn][Fn];              // sh + ffb + sh@W^T
__device__ float4 g_Bq0[Bn][4096];           // packed tf32 B frag pairs (GEMM0)
__device__ float4 g_Bq1[Bn][4096];           // packed tf32 B frag pairs (GEMM1)

__device__ __forceinline__ uint32_t smem_u32(const void* p) {
    uint32_t a;
    asm("{ .reg .u64 t; cvta.to.shared.u64 t, %1; cvt.u32.u64 %0, t; }" : "=r"(a) : "l"(p));
    return a;
}
__device__ __forceinline__ uint32_t f2tf32(float x) {
    uint32_t r;
    asm("cvt.rna.tf32.f32 %0, %1;" : "=r"(r) : "f"(x));
    return r;
}
__device__ __forceinline__ float tfr(float x) {   // tf32-rounded value as float
    return __uint_as_float(f2tf32(x));
}
__device__ __forceinline__ void cp16(uint32_t dst, const void* src) {
    asm volatile("cp.async.cg.shared.global [%0], [%1], 16;" :: "r"(dst), "l"(src));
}
#define CP_COMMIT() asm volatile("cp.async.commit_group;" ::: "memory")
#define CP_WAIT1()  asm volatile("cp.async.wait_group 1;" ::: "memory")

#define LDSM4(r0, r1, r2, r3, addr) \
    asm volatile("ldmatrix.sync.aligned.m8n8.x4.shared.b16 {%0,%1,%2,%3}, [%4];" \
                 : "=r"(r0), "=r"(r1), "=r"(r2), "=r"(r3) : "r"(addr))

#define MMA_TF32(C, A, b0, b1) \
    asm volatile("mma.sync.aligned.m16n8k8.row.col.f32.tf32.tf32.f32 " \
                 "{%0,%1,%2,%3}, {%4,%5,%6,%7}, {%8,%9}, {%0,%1,%2,%3};" \
                 : "+f"(C[0]), "+f"(C[1]), "+f"(C[2]), "+f"(C[3]) \
                 : "r"(A[0]), "r"(A[1]), "r"(A[2]), "r"(A[3]), "r"(b0), "r"(b1))

// ---------------- 1) wavelet coefficients + biases ----------------
__global__ void coef_kernel(const float* __restrict__ qw, const float* __restrict__ qb,
                            const float* __restrict__ kw, const float* __restrict__ kb) {
    int l = blockIdx.x * blockDim.x + threadIdx.x;
    if (l < Ln) {
        float cq = 1.f, ck = 1.f;
        #pragma unroll
        for (int i = 0; i < NLEV; i++) {
            int bit = (l >> i) & 1;
            cq *= qw[2 * i + bit];
            ck *= kw[2 * i + bit];
        }
        g_coef[0][l] = cq;
        g_coef[1][l] = ck;
    }
    if (blockIdx.x == 0 && threadIdx.x == 0) {
        float bq = qb[NLEV - 1], bk = kb[NLEV - 1], pq = 1.f, pk = 1.f;
        for (int i = NLEV - 2; i >= 0; i--) {
            pq *= (qw[2 * (i + 1)] + qw[2 * (i + 1) + 1]);
            pk *= (kw[2 * (i + 1)] + kw[2 * (i + 1) + 1]);
            bq += qb[i] * pq;
            bk += kb[i] * pk;
        }
        g_bias[0] = bq;
        g_bias[1] = bk;
    }
}

// ---------------- 2) q/k partial reductions over L ----------------
__global__ void qk_partial(const float* __restrict__ x) {
    const int b = blockIdx.y, ls = blockIdx.x;
    const int tid = threadIdx.x;
    const int f = tid & 127, sub = tid >> 7;
    const int lbase = ls * 256 + sub * 128;
    const float* xp = x + ((size_t)b * Ln + lbase) * Fn + f;
    float aq = 0.f, ak = 0.f;
    #pragma unroll 8
    for (int j = 0; j < 128; j++) {
        float xv = xp[(size_t)j * Fn];
        int l = lbase + j;
        aq = fmaf(g_coef[0][l], xv, aq);
        ak = fmaf(g_coef[1][l], xv, ak);
    }
    __shared__ float sq[256], sk[256];
    sq[tid] = aq; sk[tid] = ak;
    __syncthreads();
    if (tid < 128) {
        g_part[b][ls][0][tid] = sq[tid] + sq[tid + 128];
        g_part[b][ls][1][tid] = sk[tid] + sk[tid + 128];
    }
}

// ---------------- 3a) q/k finalize ----------------
__global__ void att_qk() {
    const int b = blockIdx.x, f = threadIdx.x;
    float q = g_bias[0], k = g_bias[1];
    #pragma unroll
    for (int s = 0; s < NSPLIT; s++) {
        q += g_part[b][s][0][f];
        k += g_part[b][s][1][f];
    }
    g_qs[b][f] = q * 0.08838834764831845f;
    g_kv[b][f] = k;
}

// ---------------- 3b) softmax rows + packed B0 table (256 CTAs) ----------------
// CTA (r, b): handles att rows (k-indices) r*16 .. r*16+15
__global__ void att_soft() {
    __shared__ float kk[Fn];
    __shared__ float at[16][132];
    __shared__ float ri[16];
    const int r = blockIdx.x, b = blockIdx.y;
    const int t = threadIdx.x;
    kk[t] = g_kv[b][t];
    __syncthreads();

    const int row = t >> 3, c = t & 7;           // 16 rows x 8 threads
    const float tq = g_qs[b][r * 16 + row];
    float e[16];
    float m = -1e30f;
    #pragma unroll
    for (int j = 0; j < 16; j++) {
        e[j] = tq * kk[c * 16 + j];
        m = fmaxf(m, e[j]);
    }
    #pragma unroll
    for (int off = 1; off < 8; off <<= 1)
        m = fmaxf(m, __shfl_xor_sync(0xFFFFFFFFu, m, off));
    float sum = 0.f;
    #pragma unroll
    for (int j = 0; j < 16; j++) {
        e[j] = expf(e[j] - m);
        at[row][c * 16 + j] = e[j];
        sum += e[j];
    }
    #pragma unroll
    for (int off = 1; off < 8; off <<= 1)
        sum += __shfl_xor_sync(0xFFFFFFFFu, sum, off);
    if (c == 0) ri[row] = 1.f / sum;
    __syncthreads();

    // table entries: idx = wn*1024 + np*512 + ks*32 + lane, ks = 2r + kk2
    #pragma unroll
    for (int eidx = 0; eidx < 4; eidx++) {
        int ee = t + eidx * 128;                 // 0..511
        int lane = ee & 31, kk2 = (ee >> 5) & 1, np = (ee >> 6) & 1, wn = ee >> 7;
        int gd = lane >> 2, tg = lane & 3;
        int kr0 = kk2 * 8 + tg, kr1 = kr0 + 4;
        int nA = wn * 32 + np * 16 + gd, nB = nA + 8;
        float4 v;
        v.x = tfr(at[kr0][nA] * ri[kr0]);
        v.y = tfr(at[kr1][nA] * ri[kr1]);
        v.z = tfr(at[kr0][nB] * ri[kr0]);
        v.w = tfr(at[kr1][nB] * ri[kr1]);
        g_Bq0[b][wn * 1024 + np * 512 + (r * 2 + kk2) * 32 + lane] = v;
    }
}

// ---------------- 4a) stat finalize + rsh ----------------
__global__ void prep2a(const float* __restrict__ ffw, const float* __restrict__ ffb,
                       const float* __restrict__ gamma, const float* __restrict__ beta) {
    __shared__ float ssh[Fn];
    const int b = blockIdx.x, g = threadIdx.x;
    float s = 0.f, q = 0.f;
    #pragma unroll
    for (int t = 0; t < GRIDX; t++) {
        s += g_stat[b][t][0][g];
        q += g_stat[b][t][1][g];
    }
    const float inv = 1.f / (float)Ln;
    float m = s * inv;
    float v = q * inv - m * m;
    float rs = rsqrtf(v + 1e-5f);
    float sc = rs * gamma[g];
    float sh = fmaf(-m, sc, beta[g]);
    g_sc[b][g] = sc;
    ssh[g] = sh;
    __syncthreads();
    float bias2 = ffb[g];
    const float4* wr = (const float4*)&ffw[g * Fn];
    #pragma unroll 8
    for (int k4 = 0; k4 < 32; k4++) {
        float4 wv = __ldg(wr + k4);
        bias2 = fmaf(ssh[k4 * 4],     wv.x, bias2);
        bias2 = fmaf(ssh[k4 * 4 + 1], wv.y, bias2);
        bias2 = fmaf(ssh[k4 * 4 + 2], wv.z, bias2);
        bias2 = fmaf(ssh[k4 * 4 + 3], wv.w, bias2);
    }
    g_rsh[b][g] = ssh[g] + bias2;
}

// ---------------- 4b) packed B1 table: B1[n][k] = ffw[n][k]*sc[k] (256 CTAs) ----------------
__global__ void prep2b(const float* __restrict__ ffw) {
    __shared__ float ssc[Fn];
    const int r = blockIdx.x, b = blockIdx.y;
    const int t = threadIdx.x;
    ssc[t] = g_sc[b][t];
    __syncthreads();
    #pragma unroll
    for (int eidx = 0; eidx < 4; eidx++) {
        int ee = t + eidx * 128;
        int lane = ee & 31, kk2 = (ee >> 5) & 1, np = (ee >> 6) & 1, wn = ee >> 7;
        int gd = lane >> 2, tg = lane & 3;
        int k0 = (r * 2 + kk2) * 8 + tg, k1 = k0 + 4;
        int nA = wn * 32 + np * 16 + gd, nB = nA + 8;
        float4 v;
        v.x = tfr(__ldg(&ffw[nA * Fn + k0]) * ssc[k0]);
        v.y = tfr(__ldg(&ffw[nA * Fn + k1]) * ssc[k1]);
        v.z = tfr(__ldg(&ffw[nB * Fn + k0]) * ssc[k0]);
        v.w = tfr(__ldg(&ffw[nB * Fn + k1]) * ssc[k1]);
        g_Bq1[b][wn * 1024 + np * 512 + (r * 2 + kk2) * 32 + lane] = v;
    }
}

// ---------------- 5) tf32 GEMM: 128x128 tile, ldmatrix A, float4 LDG B ----------------
// out = (A @ B^T) + A*rsc + rsh ; MODE0: rsc=1, rsh=0
template <int MODE>
__global__ __launch_bounds__(512, 1)
void mma_gemm(const float* __restrict__ xin) {
    extern __shared__ float sm[];
    float* const Abuf[2] = { sm, sm + FO_A1 };
    float4* const red = (float4*)(sm + FO_RED);

    const int tid = threadIdx.x, lane = tid & 31, w = tid >> 5;
    const int gid = lane >> 2, tig = lane & 3;
    const int wm = w >> 2, wn = w & 3;           // 4 wm x 4 wn, warp tile 32x32
    const int b = blockIdx.y;

    const size_t base = ((size_t)b * Ln + (size_t)blockIdx.x * TILES_PER_CTA * TILE_L) * Fn;
    const float* Xin = (MODE == 0 ? xin : g_x2) + base;
    float* Xout = (MODE == 0 ? g_x2 : g_y3) + base;

    const uint32_t ab32[2] = { smem_u32(Abuf[0]), smem_u32(Abuf[1]) };

    // ldmatrix per-thread source offset (bytes)
    const uint32_t lrow = lane & 15;
    const uint32_t lcol = (lane >> 4) * 4;
    const uint32_t aoff = ((wm * 32 + lrow) * 132 + lcol) * 4;

    // packed B fragment-pair pointer
    const float4* Bq = (MODE == 0 ? &g_Bq0[b][0] : &g_Bq1[b][0]) + wn * 1024 + lane;

    // prologue: cp.async tile 0 (128x128 floats = 4096 float4)
    #pragma unroll
    for (int i = tid; i < 4096; i += 512)
        cp16(ab32[0] + ((i >> 5) * 132 + (i & 31) * 4) * 4, Xin + (size_t)i * 4);
    CP_COMMIT();

    // epilogue affine params
    float2 rsc2[4], rsh2[4];
    #pragma unroll
    for (int ni = 0; ni < 4; ni++) {
        if (MODE == 1) {
            int col = wn * 32 + ni * 8 + tig * 2;
            rsc2[ni] = *(const float2*)&g_sc[b][col];
            rsh2[ni] = *(const float2*)&g_rsh[b][col];
        } else {
            rsc2[ni] = make_float2(1.f, 1.f);
            rsh2[ni] = make_float2(0.f, 0.f);
        }
    }

    float2 st_s[4], st_q[4];
    #pragma unroll
    for (int ni = 0; ni < 4; ni++) {
        st_s[ni] = make_float2(0.f, 0.f);
        st_q[ni] = make_float2(0.f, 0.f);
    }

    for (int t = 0; t < TILES_PER_CTA; t++) {
        if (t + 1 < TILES_PER_CTA) {
            const float* src = Xin + (size_t)(t + 1) * TILE_L * Fn;
            #pragma unroll
            for (int i = tid; i < 4096; i += 512)
                cp16(ab32[(t + 1) & 1] + ((i >> 5) * 132 + (i & 31) * 4) * 4, src + (size_t)i * 4);
        }
        CP_COMMIT();
        CP_WAIT1();
        __syncthreads();

        const uint32_t abase = ab32[t & 1] + aoff;
        float* const buf = Abuf[t & 1];

        float c[2][4][4];
        #pragma unroll
        for (int mi = 0; mi < 2; mi++)
            #pragma unroll
            for (int ni = 0; ni < 4; ni++)
                #pragma unroll
                for (int j = 0; j < 4; j++) c[mi][ni][j] = 0.f;

        #pragma unroll
        for (int ks = 0; ks < 16; ks++) {
            uint32_t a[2][4];
            LDSM4(a[0][0], a[0][1], a[0][2], a[0][3], abase + ks * 32);
            LDSM4(a[1][0], a[1][1], a[1][2], a[1][3], abase + 16 * 132 * 4 + ks * 32);
            #pragma unroll
            for (int mi = 0; mi < 2; mi++)
                #pragma unroll
                for (int j = 0; j < 4; j++)
                    a[mi][j] = f2tf32(__uint_as_float(a[mi][j]));
            #pragma unroll
            for (int np = 0; np < 2; np++) {
                float4 bv = __ldg(Bq + np * 512 + ks * 32);
                uint32_t b0 = __float_as_uint(bv.x), b1 = __float_as_uint(bv.y);
                uint32_t b2 = __float_as_uint(bv.z), b3 = __float_as_uint(bv.w);
                MMA_TF32(c[0][2 * np],     a[0], b0, b1);
                MMA_TF32(c[0][2 * np + 1], a[0], b2, b3);
                MMA_TF32(c[1][2 * np],     a[1], b0, b1);
                MMA_TF32(c[1][2 * np + 1], a[1], b2, b3);
            }
        }

        // direct epilogue: residual from A smem, STG to gmem, stats in regs
        float* Yt = Xout + (size_t)t * TILE_L * Fn;
        #pragma unroll
        for (int mi = 0; mi < 2; mi++)
            #pragma unroll
            for (int ni = 0; ni < 4; ni++) {
                const int r0 = wm * 32 + mi * 16 + gid;
                const int col = wn * 32 + ni * 8 + tig * 2;
                float2 x0 = *(float2*)&buf[r0 * 132 + col];
                float2 x1 = *(float2*)&buf[(r0 + 8) * 132 + col];
                float2 o0, o1;
                o0.x = c[mi][ni][0] + fmaf(x0.x, rsc2[ni].x, rsh2[ni].x);
                o0.y = c[mi][ni][1] + fmaf(x0.y, rsc2[ni].y, rsh2[ni].y);
                o1.x = c[mi][ni][2] + fmaf(x1.x, rsc2[ni].x, rsh2[ni].x);
                o1.y = c[mi][ni][3] + fmaf(x1.y, rsc2[ni].y, rsh2[ni].y);
                *(float2*)&Yt[(size_t)r0 * Fn + col] = o0;
                *(float2*)&Yt[(size_t)(r0 + 8) * Fn + col] = o1;
                st_s[ni].x += o0.x + o1.x;
                st_s[ni].y += o0.y + o1.y;
                st_q[ni].x += fmaf(o0.x, o0.x, o1.x * o1.x);
                st_q[ni].y += fmaf(o0.y, o0.y, o1.y * o1.y);
            }
        __syncthreads();
    }

    // stats: shfl over gid (offsets 4,8,16), then cross-wm via smem
    #pragma unroll
    for (int ni = 0; ni < 4; ni++) {
        #pragma unroll
        for (int off = 4; off < 32; off <<= 1) {
            st_s[ni].x += __shfl_xor_sync(0xFFFFFFFFu, st_s[ni].x, off);
            st_s[ni].y += __shfl_xor_sync(0xFFFFFFFFu, st_s[ni].y, off);
            st_q[ni].x += __shfl_xor_sync(0xFFFFFFFFu, st_q[ni].x, off);
            st_q[ni].y += __shfl_xor_sync(0xFFFFFFFFu, st_q[ni].y, off);
        }
        if (gid == 0)
            red[w * 16 + ni * 4 + tig] = make_float4(st_s[ni].x, st_s[ni].y, st_q[ni].x, st_q[ni].y);
    }
    __syncthreads();
    if (tid < 128) {
        const int f = tid;
        const int fwn = f >> 5, fni = (f >> 3) & 3, ftg = (f >> 1) & 3, xy = f & 1;
        float s = 0.f, q = 0.f;
        #pragma unroll
        for (int m = 0; m < 4; m++) {   // over wm
            float4 v = red[(m * 4 + fwn) * 16 + fni * 4 + ftg];
            s += xy ? v.y : v.x;
            q += xy ? v.w : v.z;
        }
        g_stat[b][blockIdx.x][0][f] = s;
        g_stat[b][blockIdx.x][1][f] = q;
    }
}

// ---------------- 6) stats -> scale/shift (for final norm) ----------------
__global__ void stat_reduce(const float* __restrict__ gamma, const float* __restrict__ beta) {
    const int b = blockIdx.x, g = threadIdx.x;
    float s = 0.f, q = 0.f;
    #pragma unroll
    for (int t = 0; t < GRIDX; t++) {
        s += g_stat[b][t][0][g];
        q += g_stat[b][t][1][g];
    }
    const float inv = 1.f / (float)Ln;
    float m = s * inv;
    float v = q * inv - m * m;
    float rs = rsqrtf(v + 1e-5f);
    float sc = rs * gamma[g];
    g_sc[b][g] = sc;
    g_sh[b][g] = fmaf(-m, sc, beta[g]);
}

// ---------------- 7) final normalize ----------------
__global__ void final_kernel(float* __restrict__ out) {
    int i = blockIdx.x * blockDim.x + threadIdx.x;
    int b = i >> 17;
    int fq = i & 31;
    float4 v = ((const float4*)g_y3)[i];
    float4 s = ((const float4*)&g_sc[b][0])[fq];
    float4 h = ((const float4*)&g_sh[b][0])[fq];
    v.x = fmaf(v.x, s.x, h.x); v.y = fmaf(v.y, s.y, h.y);
    v.z = fmaf(v.z, s.z, h.z); v.w = fmaf(v.w, s.w, h.w);
    ((float4*)out)[i] = v;
}

// ---------------- launch ----------------
extern "C" void kernel_launch(void* const* d_in, const int* in_sizes, int n_in,
                              void* d_out, int out_size) {
    const float* x     = (const float*)d_in[0];
    const float* qw    = (const float*)d_in[1];
    const float* qb    = (const float*)d_in[2];
    const float* kw    = (const float*)d_in[3];
    const float* kb    = (const float*)d_in[4];
    const float* ffw   = (const float*)d_in[5];
    const float* ffb   = (const float*)d_in[6];
    const float* gamma = (const float*)d_in[7];
    const float* beta  = (const float*)d_in[8];
    float* out = (float*)d_out;

    cudaFuncSetAttribute((const void*)mma_gemm<0>,
                         cudaFuncAttributeMaxDynamicSharedMemorySize, GEMM_SMEM);
    cudaFuncSetAttribute((const void*)mma_gemm<1>,
                         cudaFuncAttributeMaxDynamicSharedMemorySize, GEMM_SMEM);

    coef_kernel<<<(Ln + 255) / 256, 256>>>(qw, qb, kw, kb);
    qk_partial<<<dim3(NSPLIT, Bn), 256>>>(x);
    att_qk<<<Bn, Fn>>>();
    att_soft<<<dim3(8, Bn), 128>>>();
    mma_gemm<0><<<dim3(GRIDX, Bn), 512, GEMM_SMEM>>>(x);
    prep2a<<<Bn, Fn>>>(ffw, ffb, gamma, beta);
    prep2b<<<dim3(8, Bn), 128>>>(ffw);
    mma_gemm<1><<<dim3(GRIDX, Bn), 512, GEMM_SMEM>>>(x);
    stat_reduce<<<Bn, Fn>>>(gamma, beta);
    final_kernel<<<TOT / 4 / 256, 256>>>(out);
}

// round 11
// speedup vs baseline: 1.2217x; 1.0306x over previous
#include <cuda_runtime.h>
#include <cstdint>

#define Bn 32
#define Ln 4096
#define Fn 128
#define NLEV 12
#define NSPLIT 16
#define TILE_L 128
#define TILES_PER_CTA 8
#define GRIDX 4                          // 4 * 8 * 128 = 4096 rows
#define TOT (Bn * Ln * Fn)

// GEMM smem: A double buffer 2 x 128x132 floats, red 1024 floats
#define FO_A1 16896
#define FO_RED 33792
#define GEMM_SMEM ((33792 + 1024) * 4)   // 139264 bytes

// ---------------- scratch ----------------
__device__ float g_coef[2][Ln];
__device__ float g_bias[2];
__device__ float g_part[Bn][NSPLIT][2][Fn];
__device__ float g_qs[Bn][Fn];               // q * 1/sqrt(F)
__device__ float g_kv[Bn][Fn];
__device__ float g_x2[TOT];
__device__ float g_y3[TOT];
__device__ float g_stat[Bn][GRIDX][2][Fn];
__device__ float g_sc[Bn][Fn];
__device__ float g_sh[Bn][Fn];
__device__ float g_rsh[Bn][Fn];              // sh + ffb + sh@W^T
__device__ float4 g_Bq0[Bn][4096];           // packed tf32 B frag pairs (GEMM0)
__device__ float4 g_Bq1[Bn][4096];           // packed tf32 B frag pairs (GEMM1)

__device__ __forceinline__ uint32_t smem_u32(const void* p) {
    uint32_t a;
    asm("{ .reg .u64 t; cvta.to.shared.u64 t, %1; cvt.u32.u64 %0, t; }" : "=r"(a) : "l"(p));
    return a;
}
__device__ __forceinline__ uint32_t f2tf32(float x) {
    uint32_t r;
    asm("cvt.rna.tf32.f32 %0, %1;" : "=r"(r) : "f"(x));
    return r;
}
__device__ __forceinline__ float tfr(float x) {   // tf32-rounded value as float
    return __uint_as_float(f2tf32(x));
}
__device__ __forceinline__ void cp16(uint32_t dst, const void* src) {
    asm volatile("cp.async.cg.shared.global [%0], [%1], 16;" :: "r"(dst), "l"(src));
}
#define CP_COMMIT() asm volatile("cp.async.commit_group;" ::: "memory")
#define CP_WAIT1()  asm volatile("cp.async.wait_group 1;" ::: "memory")
#define CP_WAIT0()  asm volatile("cp.async.wait_group 0;" ::: "memory")

#define LDSM4(r0, r1, r2, r3, addr) \
    asm volatile("ldmatrix.sync.aligned.m8n8.x4.shared.b16 {%0,%1,%2,%3}, [%4];" \
                 : "=r"(r0), "=r"(r1), "=r"(r2), "=r"(r3) : "r"(addr))

#define MMA_TF32(C, A, b0, b1) \
    asm volatile("mma.sync.aligned.m16n8k8.row.col.f32.tf32.tf32.f32 " \
                 "{%0,%1,%2,%3}, {%4,%5,%6,%7}, {%8,%9}, {%0,%1,%2,%3};" \
                 : "+f"(C[0]), "+f"(C[1]), "+f"(C[2]), "+f"(C[3]) \
                 : "r"(A[0]), "r"(A[1]), "r"(A[2]), "r"(A[3]), "r"(b0), "r"(b1))

// ---------------- 1) wavelet coefficients + biases ----------------
__global__ void coef_kernel(const float* __restrict__ qw, const float* __restrict__ qb,
                            const float* __restrict__ kw, const float* __restrict__ kb) {
    int l = blockIdx.x * blockDim.x + threadIdx.x;
    if (l < Ln) {
        float cq = 1.f, ck = 1.f;
        #pragma unroll
        for (int i = 0; i < NLEV; i++) {
            int bit = (l >> i) & 1;
            cq *= qw[2 * i + bit];
            ck *= kw[2 * i + bit];
        }
        g_coef[0][l] = cq;
        g_coef[1][l] = ck;
    }
    if (blockIdx.x == 0 && threadIdx.x == 0) {
        float bq = qb[NLEV - 1], bk = kb[NLEV - 1], pq = 1.f, pk = 1.f;
        for (int i = NLEV - 2; i >= 0; i--) {
            pq *= (qw[2 * (i + 1)] + qw[2 * (i + 1) + 1]);
            pk *= (kw[2 * (i + 1)] + kw[2 * (i + 1) + 1]);
            bq += qb[i] * pq;
            bk += kb[i] * pk;
        }
        g_bias[0] = bq;
        g_bias[1] = bk;
    }
}

// ---------------- 2) q/k partial reductions over L ----------------
__global__ void qk_partial(const float* __restrict__ x) {
    const int b = blockIdx.y, ls = blockIdx.x;
    const int tid = threadIdx.x;
    const int f = tid & 127, sub = tid >> 7;
    const int lbase = ls * 256 + sub * 128;
    const float* xp = x + ((size_t)b * Ln + lbase) * Fn + f;
    float aq = 0.f, ak = 0.f;
    #pragma unroll 8
    for (int j = 0; j < 128; j++) {
        float xv = xp[(size_t)j * Fn];
        int l = lbase + j;
        aq = fmaf(g_coef[0][l], xv, aq);
        ak = fmaf(g_coef[1][l], xv, ak);
    }
    __shared__ float sq[256], sk[256];
    sq[tid] = aq; sk[tid] = ak;
    __syncthreads();
    if (tid < 128) {
        g_part[b][ls][0][tid] = sq[tid] + sq[tid + 128];
        g_part[b][ls][1][tid] = sk[tid] + sk[tid + 128];
    }
}

// ---------------- 3a) q/k finalize ----------------
__global__ void att_qk() {
    const int b = blockIdx.x, f = threadIdx.x;
    float q = g_bias[0], k = g_bias[1];
    #pragma unroll
    for (int s = 0; s < NSPLIT; s++) {
        q += g_part[b][s][0][f];
        k += g_part[b][s][1][f];
    }
    g_qs[b][f] = q * 0.08838834764831845f;
    g_kv[b][f] = k;
}

// ---------------- 3b) softmax rows + packed B0 table (256 CTAs) ----------------
__global__ void att_soft() {
    __shared__ float kk[Fn];
    __shared__ float at[16][132];
    __shared__ float ri[16];
    const int r = blockIdx.x, b = blockIdx.y;
    const int t = threadIdx.x;
    kk[t] = g_kv[b][t];
    __syncthreads();

    const int row = t >> 3, c = t & 7;           // 16 rows x 8 threads
    const float tq = g_qs[b][r * 16 + row];
    float e[16];
    float m = -1e30f;
    #pragma unroll
    for (int j = 0; j < 16; j++) {
        e[j] = tq * kk[c * 16 + j];
        m = fmaxf(m, e[j]);
    }
    #pragma unroll
    for (int off = 1; off < 8; off <<= 1)
        m = fmaxf(m, __shfl_xor_sync(0xFFFFFFFFu, m, off));
    float sum = 0.f;
    #pragma unroll
    for (int j = 0; j < 16; j++) {
        e[j] = expf(e[j] - m);
        at[row][c * 16 + j] = e[j];
        sum += e[j];
    }
    #pragma unroll
    for (int off = 1; off < 8; off <<= 1)
        sum += __shfl_xor_sync(0xFFFFFFFFu, sum, off);
    if (c == 0) ri[row] = 1.f / sum;
    __syncthreads();

    #pragma unroll
    for (int eidx = 0; eidx < 4; eidx++) {
        int ee = t + eidx * 128;                 // 0..511
        int lane = ee & 31, kk2 = (ee >> 5) & 1, np = (ee >> 6) & 1, wn = ee >> 7;
        int gd = lane >> 2, tg = lane & 3;
        int kr0 = kk2 * 8 + tg, kr1 = kr0 + 4;
        int nA = wn * 32 + np * 16 + gd, nB = nA + 8;
        float4 v;
        v.x = tfr(at[kr0][nA] * ri[kr0]);
        v.y = tfr(at[kr1][nA] * ri[kr1]);
        v.z = tfr(at[kr0][nB] * ri[kr0]);
        v.w = tfr(at[kr1][nB] * ri[kr1]);
        g_Bq0[b][wn * 1024 + np * 512 + (r * 2 + kk2) * 32 + lane] = v;
    }
}

// ---------------- 4a) stat finalize + rsh ----------------
__global__ void prep2a(const float* __restrict__ ffw, const float* __restrict__ ffb,
                       const float* __restrict__ gamma, const float* __restrict__ beta) {
    __shared__ float ssh[Fn];
    const int b = blockIdx.x, g = threadIdx.x;
    float s = 0.f, q = 0.f;
    #pragma unroll
    for (int t = 0; t < GRIDX; t++) {
        s += g_stat[b][t][0][g];
        q += g_stat[b][t][1][g];
    }
    const float inv = 1.f / (float)Ln;
    float m = s * inv;
    float v = q * inv - m * m;
    float rs = rsqrtf(v + 1e-5f);
    float sc = rs * gamma[g];
    float sh = fmaf(-m, sc, beta[g]);
    g_sc[b][g] = sc;
    ssh[g] = sh;
    __syncthreads();
    float bias2 = ffb[g];
    const float4* wr = (const float4*)&ffw[g * Fn];
    #pragma unroll 8
    for (int k4 = 0; k4 < 32; k4++) {
        float4 wv = __ldg(wr + k4);
        bias2 = fmaf(ssh[k4 * 4],     wv.x, bias2);
        bias2 = fmaf(ssh[k4 * 4 + 1], wv.y, bias2);
        bias2 = fmaf(ssh[k4 * 4 + 2], wv.z, bias2);
        bias2 = fmaf(ssh[k4 * 4 + 3], wv.w, bias2);
    }
    g_rsh[b][g] = ssh[g] + bias2;
}

// ---------------- 4b) packed B1 table (256 CTAs) ----------------
__global__ void prep2b(const float* __restrict__ ffw) {
    __shared__ float ssc[Fn];
    const int r = blockIdx.x, b = blockIdx.y;
    const int t = threadIdx.x;
    ssc[t] = g_sc[b][t];
    __syncthreads();
    #pragma unroll
    for (int eidx = 0; eidx < 4; eidx++) {
        int ee = t + eidx * 128;
        int lane = ee & 31, kk2 = (ee >> 5) & 1, np = (ee >> 6) & 1, wn = ee >> 7;
        int gd = lane >> 2, tg = lane & 3;
        int k0 = (r * 2 + kk2) * 8 + tg, k1 = k0 + 4;
        int nA = wn * 32 + np * 16 + gd, nB = nA + 8;
        float4 v;
        v.x = tfr(__ldg(&ffw[nA * Fn + k0]) * ssc[k0]);
        v.y = tfr(__ldg(&ffw[nA * Fn + k1]) * ssc[k1]);
        v.z = tfr(__ldg(&ffw[nB * Fn + k0]) * ssc[k0]);
        v.w = tfr(__ldg(&ffw[nB * Fn + k1]) * ssc[k1]);
        g_Bq1[b][wn * 1024 + np * 512 + (r * 2 + kk2) * 32 + lane] = v;
    }
}

// ---------------- 5) tf32 GEMM: 128x128 tile, ldmatrix A (raw fp32 -> HW trunc) ----------------
// out = (A @ B^T) + A*rsc + rsh ; MODE0: rsc=1, rsh=0
template <int MODE>
__global__ __launch_bounds__(512, 1)
void mma_gemm(const float* __restrict__ xin) {
    extern __shared__ float sm[];
    float* const Abuf[2] = { sm, sm + FO_A1 };
    float4* const red = (float4*)(sm + FO_RED);

    const int tid = threadIdx.x, lane = tid & 31, w = tid >> 5;
    const int gid = lane >> 2, tig = lane & 3;
    const int wm = w >> 2, wn = w & 3;           // 4 wm x 4 wn, warp tile 32x32
    const int b = blockIdx.y;

    const size_t base = ((size_t)b * Ln + (size_t)blockIdx.x * TILES_PER_CTA * TILE_L) * Fn;
    const float* Xin = (MODE == 0 ? xin : g_x2) + base;
    float* Xout = (MODE == 0 ? g_x2 : g_y3) + base;

    const uint32_t ab32[2] = { smem_u32(Abuf[0]), smem_u32(Abuf[1]) };

    const uint32_t lrow = lane & 15;
    const uint32_t lcol = (lane >> 4) * 4;
    const uint32_t aoff = ((wm * 32 + lrow) * 132 + lcol) * 4;

    const float4* Bq = (MODE == 0 ? &g_Bq0[b][0] : &g_Bq1[b][0]) + wn * 1024 + lane;

    // prologue: cp.async tile 0
    #pragma unroll
    for (int i = tid; i < 4096; i += 512)
        cp16(ab32[0] + ((i >> 5) * 132 + (i & 31) * 4) * 4, Xin + (size_t)i * 4);
    CP_COMMIT();

    float2 rsc2[4], rsh2[4];
    #pragma unroll
    for (int ni = 0; ni < 4; ni++) {
        if (MODE == 1) {
            int col = wn * 32 + ni * 8 + tig * 2;
            rsc2[ni] = *(const float2*)&g_sc[b][col];
            rsh2[ni] = *(const float2*)&g_rsh[b][col];
        } else {
            rsc2[ni] = make_float2(1.f, 1.f);
            rsh2[ni] = make_float2(0.f, 0.f);
        }
    }

    float2 st_s[4], st_q[4];
    #pragma unroll
    for (int ni = 0; ni < 4; ni++) {
        st_s[ni] = make_float2(0.f, 0.f);
        st_q[ni] = make_float2(0.f, 0.f);
    }

    for (int t = 0; t < TILES_PER_CTA; t++) {
        if (t + 1 < TILES_PER_CTA) {
            const float* src = Xin + (size_t)(t + 1) * TILE_L * Fn;
            #pragma unroll
            for (int i = tid; i < 4096; i += 512)
                cp16(ab32[(t + 1) & 1] + ((i >> 5) * 132 + (i & 31) * 4) * 4, src + (size_t)i * 4);
            CP_COMMIT();
            CP_WAIT1();
        } else {
            CP_WAIT0();
        }
        __syncthreads();

        const uint32_t abase = ab32[t & 1] + aoff;
        float* const buf = Abuf[t & 1];

        float c[2][4][4];
        #pragma unroll
        for (int mi = 0; mi < 2; mi++)
            #pragma unroll
            for (int ni = 0; ni < 4; ni++)
                #pragma unroll
                for (int j = 0; j < 4; j++) c[mi][ni][j] = 0.f;

        #pragma unroll
        for (int ks = 0; ks < 16; ks++) {
            uint32_t a[2][4];
            LDSM4(a[0][0], a[0][1], a[0][2], a[0][3], abase + ks * 32);
            LDSM4(a[1][0], a[1][1], a[1][2], a[1][3], abase + 16 * 132 * 4 + ks * 32);
            // NOTE: raw fp32 registers fed to tf32 MMA — hardware truncates.
            #pragma unroll
            for (int np = 0; np < 2; np++) {
                float4 bv = __ldg(Bq + np * 512 + ks * 32);
                uint32_t b0 = __float_as_uint(bv.x), b1 = __float_as_uint(bv.y);
                uint32_t b2 = __float_as_uint(bv.z), b3 = __float_as_uint(bv.w);
                MMA_TF32(c[0][2 * np],     a[0], b0, b1);
                MMA_TF32(c[0][2 * np + 1], a[0], b2, b3);
                MMA_TF32(c[1][2 * np],     a[1], b0, b1);
                MMA_TF32(c[1][2 * np + 1], a[1], b2, b3);
            }
        }

        // direct epilogue: residual from A smem, STG to gmem, stats in regs
        float* Yt = Xout + (size_t)t * TILE_L * Fn;
        #pragma unroll
        for (int mi = 0; mi < 2; mi++)
            #pragma unroll
            for (int ni = 0; ni < 4; ni++) {
                const int r0 = wm * 32 + mi * 16 + gid;
                const int col = wn * 32 + ni * 8 + tig * 2;
                float2 x0 = *(float2*)&buf[r0 * 132 + col];
                float2 x1 = *(float2*)&buf[(r0 + 8) * 132 + col];
                float2 o0, o1;
                o0.x = c[mi][ni][0] + fmaf(x0.x, rsc2[ni].x, rsh2[ni].x);
                o0.y = c[mi][ni][1] + fmaf(x0.y, rsc2[ni].y, rsh2[ni].y);
                o1.x = c[mi][ni][2] + fmaf(x1.x, rsc2[ni].x, rsh2[ni].x);
                o1.y = c[mi][ni][3] + fmaf(x1.y, rsc2[ni].y, rsh2[ni].y);
                *(float2*)&Yt[(size_t)r0 * Fn + col] = o0;
                *(float2*)&Yt[(size_t)(r0 + 8) * Fn + col] = o1;
                st_s[ni].x += o0.x + o1.x;
                st_s[ni].y += o0.y + o1.y;
                st_q[ni].x += fmaf(o0.x, o0.x, o1.x * o1.x);
                st_q[ni].y += fmaf(o0.y, o0.y, o1.y * o1.y);
            }
        __syncthreads();
    }

    // stats: shfl over gid (offsets 4,8,16), then cross-wm via smem
    #pragma unroll
    for (int ni = 0; ni < 4; ni++) {
        #pragma unroll
        for (int off = 4; off < 32; off <<= 1) {
            st_s[ni].x += __shfl_xor_sync(0xFFFFFFFFu, st_s[ni].x, off);
            st_s[ni].y += __shfl_xor_sync(0xFFFFFFFFu, st_s[ni].y, off);
            st_q[ni].x += __shfl_xor_sync(0xFFFFFFFFu, st_q[ni].x, off);
            st_q[ni].y += __shfl_xor_sync(0xFFFFFFFFu, st_q[ni].y, off);
        }
        if (gid == 0)
            red[w * 16 + ni * 4 + tig] = make_float4(st_s[ni].x, st_s[ni].y, st_q[ni].x, st_q[ni].y);
    }
    __syncthreads();
    if (tid < 128) {
        const int f = tid;
        const int fwn = f >> 5, fni = (f >> 3) & 3, ftg = (f >> 1) & 3, xy = f & 1;
        float s = 0.f, q = 0.f;
        #pragma unroll
        for (int m = 0; m < 4; m++) {   // over wm
            float4 v = red[(m * 4 + fwn) * 16 + fni * 4 + ftg];
            s += xy ? v.y : v.x;
            q += xy ? v.w : v.z;
        }
        g_stat[b][blockIdx.x][0][f] = s;
        g_stat[b][blockIdx.x][1][f] = q;
    }
}

// ---------------- 6) stats -> scale/shift (for final norm) ----------------
__global__ void stat_reduce(const float* __restrict__ gamma, const float* __restrict__ beta) {
    const int b = blockIdx.x, g = threadIdx.x;
    float s = 0.f, q = 0.f;
    #pragma unroll
    for (int t = 0; t < GRIDX; t++) {
        s += g_stat[b][t][0][g];
        q += g_stat[b][t][1][g];
    }
    const float inv = 1.f / (float)Ln;
    float m = s * inv;
    float v = q * inv - m * m;
    float rs = rsqrtf(v + 1e-5f);
    float sc = rs * gamma[g];
    g_sc[b][g] = sc;
    g_sh[b][g] = fmaf(-m, sc, beta[g]);
}

// ---------------- 7) final normalize ----------------
__global__ void final_kernel(float* __restrict__ out) {
    int i = blockIdx.x * blockDim.x + threadIdx.x;
    int b = i >> 17;
    int fq = i & 31;
    float4 v = ((const float4*)g_y3)[i];
    float4 s = ((const float4*)&g_sc[b][0])[fq];
    float4 h = ((const float4*)&g_sh[b][0])[fq];
    v.x = fmaf(v.x, s.x, h.x); v.y = fmaf(v.y, s.y, h.y);
    v.z = fmaf(v.z, s.z, h.z); v.w = fmaf(v.w, s.w, h.w);
    ((float4*)out)[i] = v;
}

// ---------------- launch ----------------
extern "C" void kernel_launch(void* const* d_in, const int* in_sizes, int n_in,
                              void* d_out, int out_size) {
    const float* x     = (const float*)d_in[0];
    const float* qw    = (const float*)d_in[1];
    const float* qb    = (const float*)d_in[2];
    const float* kw    = (const float*)d_in[3];
    const float* kb    = (const float*)d_in[4];
    const float* ffw   = (const float*)d_in[5];
    const float* ffb   = (const float*)d_in[6];
    const float* gamma = (const float*)d_in[7];
    const float* beta  = (const float*)d_in[8];
    float* out = (float*)d_out;

    cudaFuncSetAttribute((const void*)mma_gemm<0>,
                         cudaFuncAttributeMaxDynamicSharedMemorySize, GEMM_SMEM);
    cudaFuncSetAttribute((const void*)mma_gemm<1>,
                         cudaFuncAttributeMaxDynamicSharedMemorySize, GEMM_SMEM);

    coef_kernel<<<(Ln + 255) / 256, 256>>>(qw, qb, kw, kb);
    qk_partial<<<dim3(NSPLIT, Bn), 256>>>(x);
    att_qk<<<Bn, Fn>>>();
    att_soft<<<dim3(8, Bn), 128>>>();
    mma_gemm<0><<<dim3(GRIDX, Bn), 512, GEMM_SMEM>>>(x);
    prep2a<<<Bn, Fn>>>(ffw, ffb, gamma, beta);
    prep2b<<<dim3(8, Bn), 128>>>(ffw);
    mma_gemm<1><<<dim3(GRIDX, Bn), 512, GEMM_SMEM>>>(x);
    stat_reduce<<<Bn, Fn>>>(gamma, beta);
    final_kernel<<<TOT / 4 / 256, 256>>>(out);
}

// round 12
// speedup vs baseline: 1.2804x; 1.0480x over previous
#include <cuda_runtime.h>
#include <cstdint>

#define Bn 32
#define Ln 4096
#define Fn 128
#define NLEV 12
#define NSPLIT 16
#define TILE_L 128
#define TILES_PER_CTA 8
#define GRIDX 4                          // 4 CTAs per batch * 8 tiles * 128 rows = 4096
#define TOT (Bn * Ln * Fn)

// smem floats: A0 [0,16896), A1 [16896,33792), red [33792,34816), tab [34816,35200)
#define FO_A1 16896
#define FO_RED 33792
#define FO_TAB 34816
#define MEGA_SMEM ((34816 + 384) * 4)    // 140800 bytes

// ---------------- scratch ----------------
__device__ float g_coef[2][Ln];
__device__ float g_bias[2];
__device__ float g_part[Bn][NSPLIT][2][Fn];
__device__ float g_qs[Bn][Fn];
__device__ float g_kv[Bn][Fn];
__device__ float g_x2[TOT];
__device__ float g_statA[Bn][GRIDX][2][Fn];
__device__ float g_statB[Bn][GRIDX][2][Fn];
__device__ float4 g_Bq0[Bn][4096];           // packed tf32 B frag pairs (GEMM0: att^T)
__device__ float4 g_BqW[4096];               // packed raw ffw frag pairs (batch-independent)
__device__ float4 g_Bq1[Bn][4096];           // packed (sc*W) frag pairs (GEMM1)
__device__ int g_cnt0[Bn];
__device__ int g_cnt1[Bn];
__device__ int g_cnt2[Bn];

__device__ __forceinline__ uint32_t smem_u32(const void* p) {
    uint32_t a;
    asm("{ .reg .u64 t; cvta.to.shared.u64 t, %1; cvt.u32.u64 %0, t; }" : "=r"(a) : "l"(p));
    return a;
}
__device__ __forceinline__ uint32_t f2tf32(float x) {
    uint32_t r;
    asm("cvt.rna.tf32.f32 %0, %1;" : "=r"(r) : "f"(x));
    return r;
}
__device__ __forceinline__ float tfr(float x) {
    return __uint_as_float(f2tf32(x));
}
__device__ __forceinline__ void cp16(uint32_t dst, const void* src) {
    asm volatile("cp.async.cg.shared.global [%0], [%1], 16;" :: "r"(dst), "l"(src));
}
#define CP_COMMIT() asm volatile("cp.async.commit_group;" ::: "memory")
#define CP_WAIT1()  asm volatile("cp.async.wait_group 1;" ::: "memory")
#define CP_WAIT0()  asm volatile("cp.async.wait_group 0;" ::: "memory")

#define LDSM4(r0, r1, r2, r3, addr) \
    asm volatile("ldmatrix.sync.aligned.m8n8.x4.shared.b16 {%0,%1,%2,%3}, [%4];" \
                 : "=r"(r0), "=r"(r1), "=r"(r2), "=r"(r3) : "r"(addr))

#define MMA_TF32(C, A, b0, b1) \
    asm volatile("mma.sync.aligned.m16n8k8.row.col.f32.tf32.tf32.f32 " \
                 "{%0,%1,%2,%3}, {%4,%5,%6,%7}, {%8,%9}, {%0,%1,%2,%3};" \
                 : "+f"(C[0]), "+f"(C[1]), "+f"(C[2]), "+f"(C[3]) \
                 : "r"(A[0]), "r"(A[1]), "r"(A[2]), "r"(A[3]), "r"(b0), "r"(b1))

// ---------------- 1) wavelet coefficients + biases + counter reset ----------------
__global__ void coef_kernel(const float* __restrict__ qw, const float* __restrict__ qb,
                            const float* __restrict__ kw, const float* __restrict__ kb) {
    int l = blockIdx.x * blockDim.x + threadIdx.x;
    if (blockIdx.x == 0 && threadIdx.x < Bn) {
        g_cnt0[threadIdx.x] = 0;
        g_cnt1[threadIdx.x] = 0;
        g_cnt2[threadIdx.x] = 0;
    }
    if (l < Ln) {
        float cq = 1.f, ck = 1.f;
        #pragma unroll
        for (int i = 0; i < NLEV; i++) {
            int bit = (l >> i) & 1;
            cq *= qw[2 * i + bit];
            ck *= kw[2 * i + bit];
        }
        g_coef[0][l] = cq;
        g_coef[1][l] = ck;
    }
    if (blockIdx.x == 0 && threadIdx.x == 0) {
        float bq = qb[NLEV - 1], bk = kb[NLEV - 1], pq = 1.f, pk = 1.f;
        for (int i = NLEV - 2; i >= 0; i--) {
            pq *= (qw[2 * (i + 1)] + qw[2 * (i + 1) + 1]);
            pk *= (kw[2 * (i + 1)] + kw[2 * (i + 1) + 1]);
            bq += qb[i] * pq;
            bk += kb[i] * pk;
        }
        g_bias[0] = bq;
        g_bias[1] = bk;
    }
}

// ---------------- 2) q/k partial reductions ----------------
__global__ void qk_partial(const float* __restrict__ x) {
    const int b = blockIdx.y, ls = blockIdx.x;
    const int tid = threadIdx.x;
    const int f = tid & 127, sub = tid >> 7;
    const int lbase = ls * 256 + sub * 128;
    const float* xp = x + ((size_t)b * Ln + lbase) * Fn + f;
    float aq = 0.f, ak = 0.f;
    #pragma unroll 8
    for (int j = 0; j < 128; j++) {
        float xv = xp[(size_t)j * Fn];
        int l = lbase + j;
        aq = fmaf(g_coef[0][l], xv, aq);
        ak = fmaf(g_coef[1][l], xv, ak);
    }
    __shared__ float sq[256], sk[256];
    sq[tid] = aq; sk[tid] = ak;
    __syncthreads();
    if (tid < 128) {
        g_part[b][ls][0][tid] = sq[tid] + sq[tid + 128];
        g_part[b][ls][1][tid] = sk[tid] + sk[tid + 128];
    }
}

// ---------------- 3a) q/k finalize ----------------
__global__ void att_qk() {
    const int b = blockIdx.x, f = threadIdx.x;
    float q = g_bias[0], k = g_bias[1];
    #pragma unroll
    for (int s = 0; s < NSPLIT; s++) {
        q += g_part[b][s][0][f];
        k += g_part[b][s][1][f];
    }
    g_qs[b][f] = q * 0.08838834764831845f;
    g_kv[b][f] = k;
}

// ---------------- 3b) softmax rows + packed B0 table ----------------
__global__ void att_soft() {
    __shared__ float kk[Fn];
    __shared__ float at[16][132];
    __shared__ float ri[16];
    const int r = blockIdx.x, b = blockIdx.y;
    const int t = threadIdx.x;
    kk[t] = g_kv[b][t];
    __syncthreads();

    const int row = t >> 3, c = t & 7;
    const float tq = g_qs[b][r * 16 + row];
    float e[16];
    float m = -1e30f;
    #pragma unroll
    for (int j = 0; j < 16; j++) {
        e[j] = tq * kk[c * 16 + j];
        m = fmaxf(m, e[j]);
    }
    #pragma unroll
    for (int off = 1; off < 8; off <<= 1)
        m = fmaxf(m, __shfl_xor_sync(0xFFFFFFFFu, m, off));
    float sum = 0.f;
    #pragma unroll
    for (int j = 0; j < 16; j++) {
        e[j] = expf(e[j] - m);
        at[row][c * 16 + j] = e[j];
        sum += e[j];
    }
    #pragma unroll
    for (int off = 1; off < 8; off <<= 1)
        sum += __shfl_xor_sync(0xFFFFFFFFu, sum, off);
    if (c == 0) ri[row] = 1.f / sum;
    __syncthreads();

    #pragma unroll
    for (int eidx = 0; eidx < 4; eidx++) {
        int ee = t + eidx * 128;
        int lane = ee & 31, kk2 = (ee >> 5) & 1, np = (ee >> 6) & 1, wn = ee >> 7;
        int gd = lane >> 2, tg = lane & 3;
        int kr0 = kk2 * 8 + tg, kr1 = kr0 + 4;
        int nA = wn * 32 + np * 16 + gd, nB = nA + 8;
        float4 v;
        v.x = tfr(at[kr0][nA] * ri[kr0]);
        v.y = tfr(at[kr1][nA] * ri[kr1]);
        v.z = tfr(at[kr0][nB] * ri[kr0]);
        v.w = tfr(at[kr1][nB] * ri[kr1]);
        g_Bq0[b][wn * 1024 + np * 512 + (r * 2 + kk2) * 32 + lane] = v;
    }
}

// ---------------- 4) raw ffw fragment table (batch-independent) ----------------
__global__ void prep_w(const float* __restrict__ ffw) {
    const int r = blockIdx.x, t = threadIdx.x;
    #pragma unroll
    for (int eidx = 0; eidx < 4; eidx++) {
        int ee = t + eidx * 128;
        int lane = ee & 31, kk2 = (ee >> 5) & 1, np = (ee >> 6) & 1, wn = ee >> 7;
        int gd = lane >> 2, tg = lane & 3;
        int k0 = (r * 2 + kk2) * 8 + tg, k1 = k0 + 4;
        int nA = wn * 32 + np * 16 + gd, nB = nA + 8;
        float4 v;
        v.x = __ldg(&ffw[nA * Fn + k0]);
        v.y = __ldg(&ffw[nA * Fn + k1]);
        v.z = __ldg(&ffw[nB * Fn + k0]);
        v.w = __ldg(&ffw[nB * Fn + k1]);
        g_BqW[wn * 1024 + np * 512 + (r * 2 + kk2) * 32 + lane] = v;
    }
}

// ---------------- GEMM tile loop (shared by both phases) ----------------
template <int MODE>
__device__ __forceinline__ void gemm_tiles(
    const float* Xin, float* Xout, const float4* Bq,
    const uint32_t* ab32, float* Ab0, float* Ab1, uint32_t aoff,
    const float2* rsc2, const float2* rsh2,
    float2* st_s, float2* st_q,
    int tid, int gid, int tig, int wm, int wn)
{
    // prologue: cp.async tile 0
    #pragma unroll
    for (int i = tid; i < 4096; i += 512)
        cp16(ab32[0] + ((i >> 5) * 132 + (i & 31) * 4) * 4, Xin + (size_t)i * 4);
    CP_COMMIT();

    for (int t = 0; t < TILES_PER_CTA; t++) {
        if (t + 1 < TILES_PER_CTA) {
            const float* src = Xin + (size_t)(t + 1) * TILE_L * Fn;
            #pragma unroll
            for (int i = tid; i < 4096; i += 512)
                cp16(ab32[(t + 1) & 1] + ((i >> 5) * 132 + (i & 31) * 4) * 4, src + (size_t)i * 4);
            CP_COMMIT();
            CP_WAIT1();
        } else {
            CP_WAIT0();
        }
        __syncthreads();

        const uint32_t abase = ab32[t & 1] + aoff;
        float* const buf = (t & 1) ? Ab1 : Ab0;

        float c[2][4][4];
        #pragma unroll
        for (int mi = 0; mi < 2; mi++)
            #pragma unroll
            for (int ni = 0; ni < 4; ni++)
                #pragma unroll
                for (int j = 0; j < 4; j++) c[mi][ni][j] = 0.f;

        #pragma unroll
        for (int ks = 0; ks < 16; ks++) {
            uint32_t a[2][4];
            LDSM4(a[0][0], a[0][1], a[0][2], a[0][3], abase + ks * 32);
            LDSM4(a[1][0], a[1][1], a[1][2], a[1][3], abase + 16 * 132 * 4 + ks * 32);
            #pragma unroll
            for (int np = 0; np < 2; np++) {
                float4 bv = __ldg(Bq + np * 512 + ks * 32);
                uint32_t b0 = __float_as_uint(bv.x), b1 = __float_as_uint(bv.y);
                uint32_t b2 = __float_as_uint(bv.z), b3 = __float_as_uint(bv.w);
                MMA_TF32(c[0][2 * np],     a[0], b0, b1);
                MMA_TF32(c[0][2 * np + 1], a[0], b2, b3);
                MMA_TF32(c[1][2 * np],     a[1], b0, b1);
                MMA_TF32(c[1][2 * np + 1], a[1], b2, b3);
            }
        }

        float* Yt = Xout + (size_t)t * TILE_L * Fn;
        #pragma unroll
        for (int mi = 0; mi < 2; mi++)
            #pragma unroll
            for (int ni = 0; ni < 4; ni++) {
                const int r0 = wm * 32 + mi * 16 + gid;
                const int col = wn * 32 + ni * 8 + tig * 2;
                float2 x0 = *(float2*)&buf[r0 * 132 + col];
                float2 x1 = *(float2*)&buf[(r0 + 8) * 132 + col];
                float2 o0, o1;
                if (MODE == 1) {
                    o0.x = c[mi][ni][0] + fmaf(x0.x, rsc2[ni].x, rsh2[ni].x);
                    o0.y = c[mi][ni][1] + fmaf(x0.y, rsc2[ni].y, rsh2[ni].y);
                    o1.x = c[mi][ni][2] + fmaf(x1.x, rsc2[ni].x, rsh2[ni].x);
                    o1.y = c[mi][ni][3] + fmaf(x1.y, rsc2[ni].y, rsh2[ni].y);
                } else {
                    o0.x = c[mi][ni][0] + x0.x;
                    o0.y = c[mi][ni][1] + x0.y;
                    o1.x = c[mi][ni][2] + x1.x;
                    o1.y = c[mi][ni][3] + x1.y;
                }
                *(float2*)&Yt[(size_t)r0 * Fn + col] = o0;
                *(float2*)&Yt[(size_t)(r0 + 8) * Fn + col] = o1;
                st_s[ni].x += o0.x + o1.x;
                st_s[ni].y += o0.y + o1.y;
                st_q[ni].x += fmaf(o0.x, o0.x, o1.x * o1.x);
                st_q[ni].y += fmaf(o0.y, o0.y, o1.y * o1.y);
            }
        __syncthreads();
    }
}

// reduce per-thread stats -> per-CTA per-feature rows (srow/qrow length 128)
__device__ __forceinline__ void reduce_stats(
    float2* st_s, float2* st_q, float4* red,
    int tid, int w, int gid, int tig, float* srow, float* qrow)
{
    #pragma unroll
    for (int ni = 0; ni < 4; ni++) {
        #pragma unroll
        for (int off = 4; off < 32; off <<= 1) {
            st_s[ni].x += __shfl_xor_sync(0xFFFFFFFFu, st_s[ni].x, off);
            st_s[ni].y += __shfl_xor_sync(0xFFFFFFFFu, st_s[ni].y, off);
            st_q[ni].x += __shfl_xor_sync(0xFFFFFFFFu, st_q[ni].x, off);
            st_q[ni].y += __shfl_xor_sync(0xFFFFFFFFu, st_q[ni].y, off);
        }
        if (gid == 0)
            red[w * 16 + ni * 4 + tig] = make_float4(st_s[ni].x, st_s[ni].y, st_q[ni].x, st_q[ni].y);
    }
    __syncthreads();
    if (tid < 128) {
        const int f = tid;
        const int fwn = f >> 5, fni = (f >> 3) & 3, ftg = (f >> 1) & 3, xy = f & 1;
        float s = 0.f, q = 0.f;
        #pragma unroll
        for (int m = 0; m < 4; m++) {
            float4 v = red[(m * 4 + fwn) * 16 + fni * 4 + ftg];
            s += xy ? v.y : v.x;
            q += xy ? v.w : v.z;
        }
        srow[f] = s;
        qrow[f] = q;
    }
    __syncthreads();
}

// ---------------- 5) persistent fused kernel: GEMM0 -> sync -> GEMM1 -> sync -> norm ----------------
__global__ __launch_bounds__(512, 1)
void mega(const float* __restrict__ x, const float* __restrict__ ffw,
          const float* __restrict__ ffb, const float* __restrict__ gamma,
          const float* __restrict__ beta, float* __restrict__ out)
{
    extern __shared__ float smm[];
    float* const Ab0 = smm;
    float* const Ab1 = smm + FO_A1;
    float4* const red = (float4*)(smm + FO_RED);
    float* const tab = smm + FO_TAB;     // [0..127] sc, [128..255] sh, [256..383] rsh

    const int tid = threadIdx.x, lane = tid & 31, w = tid >> 5;
    const int gid = lane >> 2, tig = lane & 3;
    const int wm = w >> 2, wn = w & 3;
    const int gx = blockIdx.x, b = blockIdx.y;

    const size_t base = ((size_t)b * Ln + (size_t)gx * TILES_PER_CTA * TILE_L) * Fn;
    uint32_t ab32[2] = { smem_u32(Ab0), smem_u32(Ab1) };
    const uint32_t lrow = lane & 15;
    const uint32_t lcol = (lane >> 4) * 4;
    const uint32_t aoff = ((wm * 32 + lrow) * 132 + lcol) * 4;

    float2 st_s[4], st_q[4];
    float2 unit_sc[4], zero_sh[4];
    #pragma unroll
    for (int ni = 0; ni < 4; ni++) {
        st_s[ni] = make_float2(0.f, 0.f);
        st_q[ni] = make_float2(0.f, 0.f);
        unit_sc[ni] = make_float2(1.f, 1.f);
        zero_sh[ni] = make_float2(0.f, 0.f);
    }

    // ===== phase 0: x2 = x + x @ att =====
    gemm_tiles<0>(x + base, g_x2 + base, &g_Bq0[b][0] + wn * 1024 + lane,
                  ab32, Ab0, Ab1, aoff, unit_sc, zero_sh, st_s, st_q,
                  tid, gid, tig, wm, wn);
    reduce_stats(st_s, st_q, red, tid, w, gid, tig,
                 &g_statA[b][gx][0][0], &g_statA[b][gx][1][0]);

    // sync 0: all 4 CTAs of this batch
    if (tid == 0) {
        __threadfence();
        atomicAdd(&g_cnt0[b], 1);
        while (atomicAdd(&g_cnt0[b], 0) < GRIDX) __nanosleep(64);
    }
    __syncthreads();

    // sc / sh / rsh into tab
    if (tid < 128) {
        float s = 0.f, q = 0.f;
        #pragma unroll
        for (int t = 0; t < GRIDX; t++) {
            s += g_statA[b][t][0][tid];
            q += g_statA[b][t][1][tid];
        }
        const float inv = 1.f / (float)Ln;
        float m = s * inv;
        float v = q * inv - m * m;
        float rs = rsqrtf(v + 1e-5f);
        float sc = rs * gamma[tid];
        tab[tid] = sc;
        tab[128 + tid] = fmaf(-m, sc, beta[tid]);
    }
    __syncthreads();
    if (tid < 128) {
        float bias2 = ffb[tid];
        const float4* wr = (const float4*)&ffw[tid * Fn];
        #pragma unroll 8
        for (int k4 = 0; k4 < 32; k4++) {
            float4 wv = __ldg(wr + k4);
            bias2 = fmaf(tab[128 + k4 * 4],     wv.x, bias2);
            bias2 = fmaf(tab[128 + k4 * 4 + 1], wv.y, bias2);
            bias2 = fmaf(tab[128 + k4 * 4 + 2], wv.z, bias2);
            bias2 = fmaf(tab[128 + k4 * 4 + 3], wv.w, bias2);
        }
        tab[256 + tid] = tab[128 + tid] + bias2;
    }
    __syncthreads();

    // gx==0 builds B1 table for this batch
    if (gx == 0) {
        for (int idx = tid; idx < 4096; idx += 512) {
            int ks = (idx >> 5) & 15, tg = idx & 3;
            int k0 = ks * 8 + tg, k1 = k0 + 4;
            float4 v = g_BqW[idx];
            v.x *= tab[k0]; v.y *= tab[k1];
            v.z *= tab[k0]; v.w *= tab[k1];
            g_Bq1[b][idx] = v;
        }
    }
    if (tid == 0) {
        if (gx == 0) {
            __threadfence();
            atomicAdd(&g_cnt1[b], 1);
        }
        while (atomicAdd(&g_cnt1[b], 0) < 1) __nanosleep(64);
    }
    __syncthreads();
    __threadfence();   // order our g_x2 stores before cp.async L2 reads

    // phase-1 epilogue affine params
    float2 rsc2[4], rsh2[4];
    #pragma unroll
    for (int ni = 0; ni < 4; ni++) {
        int col = wn * 32 + ni * 8 + tig * 2;
        rsc2[ni] = *(const float2*)&tab[col];
        rsh2[ni] = *(const float2*)&tab[256 + col];
        st_s[ni] = make_float2(0.f, 0.f);
        st_q[ni] = make_float2(0.f, 0.f);
    }

    // ===== phase 1: y3 = y2 + y2 @ W^T + ffb (into out, raw) =====
    gemm_tiles<1>(g_x2 + base, out + base, &g_Bq1[b][0] + wn * 1024 + lane,
                  ab32, Ab0, Ab1, aoff, rsc2, rsh2, st_s, st_q,
                  tid, gid, tig, wm, wn);
    reduce_stats(st_s, st_q, red, tid, w, gid, tig,
                 &g_statB[b][gx][0][0], &g_statB[b][gx][1][0]);

    // sync 2
    if (tid == 0) {
        __threadfence();
        atomicAdd(&g_cnt2[b], 1);
        while (atomicAdd(&g_cnt2[b], 0) < GRIDX) __nanosleep(64);
    }
    __syncthreads();

    // sc2/sh2
    if (tid < 128) {
        float s = 0.f, q = 0.f;
        #pragma unroll
        for (int t = 0; t < GRIDX; t++) {
            s += g_statB[b][t][0][tid];
            q += g_statB[b][t][1][tid];
        }
        const float inv = 1.f / (float)Ln;
        float m = s * inv;
        float v = q * inv - m * m;
        float rs = rsqrtf(v + 1e-5f);
        float sc = rs * gamma[tid];
        tab[tid] = sc;
        tab[128 + tid] = fmaf(-m, sc, beta[tid]);
    }
    __syncthreads();

    // normalize own tiles of `out` in place (L2-warm)
    const float4* s4t = (const float4*)tab;
    const float4* h4t = (const float4*)(tab + 128);
    for (int t = 0; t < TILES_PER_CTA; t++) {
        float4* Y4 = (float4*)(out + base + (size_t)t * TILE_L * Fn);
        #pragma unroll
        for (int j = 0; j < 8; j++) {
            int i = tid + 512 * j;
            float4 v = Y4[i];
            int fq = i & 31;
            float4 s = s4t[fq], h = h4t[fq];
            v.x = fmaf(v.x, s.x, h.x); v.y = fmaf(v.y, s.y, h.y);
            v.z = fmaf(v.z, s.z, h.z); v.w = fmaf(v.w, s.w, h.w);
            Y4[i] = v;
        }
    }
}

// ---------------- launch ----------------
extern "C" void kernel_launch(void* const* d_in, const int* in_sizes, int n_in,
                              void* d_out, int out_size) {
    const float* x     = (const float*)d_in[0];
    const float* qw    = (const float*)d_in[1];
    const float* qb    = (const float*)d_in[2];
    const float* kw    = (const float*)d_in[3];
    const float* kb    = (const float*)d_in[4];
    const float* ffw   = (const float*)d_in[5];
    const float* ffb   = (const float*)d_in[6];
    const float* gamma = (const float*)d_in[7];
    const float* beta  = (const float*)d_in[8];
    float* out = (float*)d_out;

    cudaFuncSetAttribute((const void*)mega,
                         cudaFuncAttributeMaxDynamicSharedMemorySize, MEGA_SMEM);

    coef_kernel<<<(Ln + 255) / 256, 256>>>(qw, qb, kw, kb);
    qk_partial<<<dim3(NSPLIT, Bn), 256>>>(x);
    att_qk<<<Bn, Fn>>>();
    att_soft<<<dim3(8, Bn), 128>>>();
    prep_w<<<8, 128>>>(ffw);
    mega<<<dim3(GRIDX, Bn), 512, MEGA_SMEM>>>(x, ffw, ffb, gamma, beta, out);
}